// round 1
// baseline (speedup 1.0000x reference)
#include <cuda_runtime.h>
#include <math.h>

#define BB 512
#define TT 200
#define HH 128
#define VV 100001
#define G3 384
#define M_TOTAL (BB*TT)   // 102400

// ---------------- scratch (static device globals; no runtime alloc) ----------------
__device__ float d_embT[(size_t)VV*HH];     // (V, H)  = emb_W^T
__device__ float d_x  [(size_t)M_TOTAL*HH]; // LN1(embedded seq feats), (B*T, H)
__device__ float d_gi [(size_t)M_TOTAL*G3]; // x @ Wih^T + bih, (B*T, 384)
__device__ float d_hs [(size_t)M_TOTAL*HH]; // GRU hidden states, (B*T, H)
__device__ float d_WihT[HH*G3];             // (K=128, N=384)

// ---------------- generic 32x32 tiled transpose:  dst(C,R) = src(R,C)^T ----------------
__global__ void transpose_kernel(const float* __restrict__ src, float* __restrict__ dst,
                                 int R, int C) {
    __shared__ float tile[32][33];
    int c0 = blockIdx.x * 32, r0 = blockIdx.y * 32;
    int tx = threadIdx.x, ty = threadIdx.y;  // (32, 8)
    #pragma unroll
    for (int j = 0; j < 32; j += 8) {
        int r = r0 + ty + j, c = c0 + tx;
        if (r < R && c < C) tile[ty + j][tx] = src[(size_t)r * C + c];
    }
    __syncthreads();
    #pragma unroll
    for (int j = 0; j < 32; j += 8) {
        int r = r0 + tx, c = c0 + ty + j;
        if (c < C && r < R) dst[(size_t)c * R + r] = tile[tx][ty + j];
    }
}

// ---------------- block-wide sum over 128 threads ----------------
__device__ __forceinline__ float blocksum128(float v, float* sb) {
    #pragma unroll
    for (int o = 16; o; o >>= 1) v += __shfl_xor_sync(0xffffffffu, v, o);
    if ((threadIdx.x & 31) == 0) sb[threadIdx.x >> 5] = v;
    __syncthreads();
    float r = sb[0] + sb[1] + sb[2] + sb[3];
    __syncthreads();
    return r;
}

// ---------------- K1: embedding gather + LayerNorm1 ----------------
__global__ void embed_ln1(const int* __restrict__ seqs,
                          const float* __restrict__ g1, const float* __restrict__ b1,
                          float* __restrict__ xout) {
    __shared__ float sb[4];
    int idx = blockIdx.x;            // b*TT + t
    int b = idx / TT, t = idx - b * TT;
    int tid = threadIdx.x;           // 128
    int tok = seqs[b * (TT + 1) + t];
    float e  = d_embT[(size_t)tok * HH + tid];
    float mu = blocksum128(e, sb) * (1.0f / HH);
    float d  = e - mu;
    float var = blocksum128(d * d, sb) * (1.0f / HH);
    float xn = d * rsqrtf(var + 1e-8f) * g1[tid] + b1[tid];
    xout[(size_t)idx * HH + tid] = xn;
}

// ---------------- K2: gi = x @ Wih^T + bih   (M=102400, N=384, K=128) ----------------
#define GP 132   // smem pitch (floats)
__global__ __launch_bounds__(256, 1)
void gemm_gi(const float* __restrict__ x, const float* __restrict__ wT,
             const float* __restrict__ bih, float* __restrict__ gi) {
    extern __shared__ float smem[];
    float* As = smem;            // [m 0..127][k pitch GP]   (m-major)
    float* Bs = smem + 128 * GP; // [k 0..127][n pitch GP]   (k-major)
    int tid = threadIdx.x;
    int tx = tid & 15, ty = tid >> 4;
    int m0 = blockIdx.x * 128;
    int n0 = blockIdx.y * 128;

    // load A tile (direct copy, float4, conflict-free)
    #pragma unroll
    for (int i = tid; i < 128 * 32; i += 256) {
        int m = i >> 5, k4 = i & 31;
        float4 v = *(const float4*)&x[((size_t)(m0 + m)) * 128 + k4 * 4];
        *(float4*)&As[m * GP + k4 * 4] = v;
    }
    // load B tile from pre-transposed WihT (k-major), float4
    #pragma unroll
    for (int i = tid; i < 128 * 32; i += 256) {
        int k = i >> 5, n4 = i & 31;
        float4 v = *(const float4*)&wT[(size_t)k * G3 + n0 + n4 * 4];
        *(float4*)&Bs[k * GP + n4 * 4] = v;
    }
    __syncthreads();

    float acc[8][8];
    #pragma unroll
    for (int i = 0; i < 8; i++)
        #pragma unroll
        for (int j = 0; j < 8; j++) acc[i][j] = 0.f;

    #pragma unroll 8
    for (int k = 0; k < 128; k++) {
        float a[8];
        #pragma unroll
        for (int i = 0; i < 4; i++) {
            a[i]     = As[(ty * 4 + i) * GP + k];
            a[4 + i] = As[(64 + ty * 4 + i) * GP + k];
        }
        float4 bv0 = *(const float4*)&Bs[k * GP + tx * 4];
        float4 bv1 = *(const float4*)&Bs[k * GP + 64 + tx * 4];
        float bvals[8] = {bv0.x, bv0.y, bv0.z, bv0.w, bv1.x, bv1.y, bv1.z, bv1.w};
        #pragma unroll
        for (int i = 0; i < 8; i++)
            #pragma unroll
            for (int j = 0; j < 8; j++)
                acc[i][j] = fmaf(a[i], bvals[j], acc[i][j]);
    }

    #pragma unroll
    for (int i = 0; i < 8; i++) {
        int m = m0 + ((i < 4) ? (ty * 4 + i) : (64 + ty * 4 + i - 4));
        #pragma unroll
        for (int j = 0; j < 8; j++) {
            int n = n0 + ((j < 4) ? (tx * 4 + j) : (64 + tx * 4 + j - 4));
            gi[(size_t)m * G3 + n] = acc[i][j] + bih[n];
        }
    }
}

// ---------------- K3: GRU recurrence. 128 CTAs x 4 sequences, 200 steps ----------------
#define WP 132   // Whh smem pitch
__global__ __launch_bounds__(512, 1)
void gru_rec(const float* __restrict__ gi, const float* __restrict__ Whh,
             const float* __restrict__ bhh, float* __restrict__ hs) {
    extern __shared__ float sm[];
    float* Wsh   = sm;                 // 384 * 132
    float* bhhsh = Wsh + 384 * WP;     // 384
    float* hsh   = bhhsh + 384;        // 4 * 128
    float* ghsh  = hsh + 512;          // 4 * 384
    int tid = threadIdx.x;             // 512
    int s0  = blockIdx.x * 4;

    for (int i = tid; i < 384 * 128; i += 512) {
        int g = i >> 7, k = i & 127;
        Wsh[g * WP + k] = Whh[i];
    }
    if (tid < 384) bhhsh[tid] = bhh[tid];
    hsh[tid] = 0.f;
    __syncthreads();

    int su = tid >> 7, ju = tid & 127;             // update-phase mapping
    size_t gibase0 = ((size_t)(s0 + su) * TT) * G3;
    size_t hsbase0 = ((size_t)(s0 + su) * TT) * HH;

    for (int t = 0; t < TT; t++) {
        // issue gi loads early: latency hides under dot phase
        size_t base = gibase0 + (size_t)t * G3;
        float ir  = gi[base + ju];
        float iz  = gi[base + 128 + ju];
        float inn = gi[base + 256 + ju];

        float acc0 = 0.f, acc1 = 0.f, acc2 = 0.f, acc3 = 0.f;
        if (tid < 384) {
            const float4* wr = (const float4*)&Wsh[tid * WP];
            #pragma unroll
            for (int k4 = 0; k4 < 32; k4++) {
                float4 w  = wr[k4];
                float4 h0 = *(const float4*)&hsh[0 * 128 + k4 * 4];
                float4 h1 = *(const float4*)&hsh[1 * 128 + k4 * 4];
                float4 h2 = *(const float4*)&hsh[2 * 128 + k4 * 4];
                float4 h3 = *(const float4*)&hsh[3 * 128 + k4 * 4];
                acc0 = fmaf(w.x, h0.x, acc0); acc0 = fmaf(w.y, h0.y, acc0);
                acc0 = fmaf(w.z, h0.z, acc0); acc0 = fmaf(w.w, h0.w, acc0);
                acc1 = fmaf(w.x, h1.x, acc1); acc1 = fmaf(w.y, h1.y, acc1);
                acc1 = fmaf(w.z, h1.z, acc1); acc1 = fmaf(w.w, h1.w, acc1);
                acc2 = fmaf(w.x, h2.x, acc2); acc2 = fmaf(w.y, h2.y, acc2);
                acc2 = fmaf(w.z, h2.z, acc2); acc2 = fmaf(w.w, h2.w, acc2);
                acc3 = fmaf(w.x, h3.x, acc3); acc3 = fmaf(w.y, h3.y, acc3);
                acc3 = fmaf(w.z, h3.z, acc3); acc3 = fmaf(w.w, h3.w, acc3);
            }
            ghsh[0 * 384 + tid] = acc0;
            ghsh[1 * 384 + tid] = acc1;
            ghsh[2 * 384 + tid] = acc2;
            ghsh[3 * 384 + tid] = acc3;
        }
        __syncthreads();

        // update phase: all 512 threads, one (seq, h-elem) each
        {
            float hr = ghsh[su * 384 + ju]        + bhhsh[ju];
            float hz = ghsh[su * 384 + 128 + ju]  + bhhsh[128 + ju];
            float hn = ghsh[su * 384 + 256 + ju]  + bhhsh[256 + ju];
            float r = 1.f / (1.f + __expf(-(ir + hr)));
            float z = 1.f / (1.f + __expf(-(iz + hz)));
            float n = tanhf(inn + r * hn);
            float hold = hsh[su * 128 + ju];
            float hnew = (1.f - z) * n + z * hold;
            hsh[su * 128 + ju] = hnew;
            hs[hsbase0 + (size_t)t * HH + ju] = hnew;
        }
        __syncthreads();
    }
}

// ---------------- K4: LayerNorm2 + pos/neg dot products ----------------
__global__ void final_logits(const int* __restrict__ seqs, const int* __restrict__ negs,
                             const float* __restrict__ g2, const float* __restrict__ b2,
                             float* __restrict__ out) {
    __shared__ float sb[4];
    int idx = blockIdx.x;           // b*TT + t
    int b = idx / TT, t = idx - b * TT;
    int tid = threadIdx.x;          // 128
    float v  = d_hs[(size_t)idx * HH + tid];
    float mu = blocksum128(v, sb) * (1.0f / HH);
    float d  = v - mu;
    float var = blocksum128(d * d, sb) * (1.0f / HH);
    float ln = d * rsqrtf(var + 1e-8f) * g2[tid] + b2[tid];

    int pt = seqs[b * (TT + 1) + t + 1];
    int nt = negs[b * (TT + 1) + t + 1];
    float pv = ln * d_embT[(size_t)pt * HH + tid];
    float nv = ln * d_embT[(size_t)nt * HH + tid];
    float ps = blocksum128(pv, sb);
    float ns = blocksum128(nv, sb);
    if (tid == 0) {
        out[idx]           = ps;
        out[M_TOTAL + idx] = ns;
    }
}

// ---------------- launch ----------------
extern "C" void kernel_launch(void* const* d_in, const int* in_sizes, int n_in,
                              void* d_out, int out_size) {
    const int*   input_seqs = (const int*)  d_in[0];
    const int*   negs       = (const int*)  d_in[1];
    const float* emb_W      = (const float*)d_in[2];
    const float* Wih        = (const float*)d_in[3];
    const float* Whh        = (const float*)d_in[4];
    const float* bih        = (const float*)d_in[5];
    const float* bhh        = (const float*)d_in[6];
    const float* ln1_g      = (const float*)d_in[7];
    const float* ln1_b      = (const float*)d_in[8];
    const float* ln2_g      = (const float*)d_in[9];
    const float* ln2_b      = (const float*)d_in[10];
    float* out = (float*)d_out;

    float* p_embT; cudaGetSymbolAddress((void**)&p_embT, d_embT);
    float* p_x;    cudaGetSymbolAddress((void**)&p_x,    d_x);
    float* p_gi;   cudaGetSymbolAddress((void**)&p_gi,   d_gi);
    float* p_hs;   cudaGetSymbolAddress((void**)&p_hs,   d_hs);
    float* p_WihT; cudaGetSymbolAddress((void**)&p_WihT, d_WihT);

    // embT = emb_W^T  (src 128 x 100001)
    transpose_kernel<<<dim3((VV + 31) / 32, 4), dim3(32, 8)>>>(emb_W, p_embT, HH, VV);
    // WihT = Wih^T    (src 384 x 128)
    transpose_kernel<<<dim3(4, 12), dim3(32, 8)>>>(Wih, p_WihT, G3, HH);

    embed_ln1<<<M_TOTAL, 128>>>(input_seqs, ln1_g, ln1_b, p_x);

    const int gemm_smem = 2 * 128 * GP * sizeof(float);   // 135168 B
    cudaFuncSetAttribute(gemm_gi, cudaFuncAttributeMaxDynamicSharedMemorySize, gemm_smem);
    gemm_gi<<<dim3(M_TOTAL / 128, 3), 256, gemm_smem>>>(p_x, p_WihT, bih, p_gi);

    const int rec_smem = (384 * WP + 384 + 512 + 4 * 384) * sizeof(float); // 212480 B
    cudaFuncSetAttribute(gru_rec, cudaFuncAttributeMaxDynamicSharedMemorySize, rec_smem);
    gru_rec<<<BB / 4, 512, rec_smem>>>(p_gi, Whh, bhh, p_hs);

    final_logits<<<M_TOTAL, 128>>>(input_seqs, negs, ln2_g, ln2_b, out);
}

// round 3
// speedup vs baseline: 1.0519x; 1.0519x over previous
#include <cuda_runtime.h>
#include <math.h>

#define BB 512
#define TT 200
#define HH 128
#define VV 100001
#define G3 384
#define M_TOTAL (BB*TT)   // 102400

// ---------------- scratch ----------------
__device__ float d_embT[(size_t)VV*HH];     // (V, H)  = emb_W^T
__device__ float d_x  [(size_t)M_TOTAL*HH]; // LN1 output
__device__ float d_gi [(size_t)M_TOTAL*G3]; // x @ Wih^T + bih
__device__ float d_hs [(size_t)M_TOTAL*HH]; // GRU hidden states
__device__ float d_WihT[HH*G3];             // (K=128, N=384)

// ---------------- packed f32x2 helpers ----------------
#define FMA2(acc, a, b) asm("fma.rn.f32x2 %0, %1, %2, %0;" : "+l"(acc) : "l"(a), "l"(b))
__device__ __forceinline__ float f2sum(unsigned long long v) {
    float lo, hi;
    asm("mov.b64 {%0,%1}, %2;" : "=f"(lo), "=f"(hi) : "l"(v));
    return lo + hi;
}
__device__ __forceinline__ unsigned long long f2dup(float a) {
    unsigned long long r;
    asm("mov.b64 %0, {%1,%1};" : "=l"(r) : "f"(a));
    return r;
}
__device__ __forceinline__ void f2unpack(unsigned long long v, float& lo, float& hi) {
    asm("mov.b64 {%0,%1}, %2;" : "=f"(lo), "=f"(hi) : "l"(v));
}

// ---------------- generic 32x32 tiled transpose ----------------
__global__ void transpose_kernel(const float* __restrict__ src, float* __restrict__ dst,
                                 int R, int C) {
    __shared__ float tile[32][33];
    int c0 = blockIdx.x * 32, r0 = blockIdx.y * 32;
    int tx = threadIdx.x, ty = threadIdx.y;  // (32, 8)
    #pragma unroll
    for (int j = 0; j < 32; j += 8) {
        int r = r0 + ty + j, c = c0 + tx;
        if (r < R && c < C) tile[ty + j][tx] = src[(size_t)r * C + c];
    }
    __syncthreads();
    #pragma unroll
    for (int j = 0; j < 32; j += 8) {
        int r = r0 + tx, c = c0 + ty + j;
        if (c < C && r < R) dst[(size_t)c * R + r] = tile[tx][ty + j];
    }
}

// ---------------- block-wide sum over 128 threads ----------------
__device__ __forceinline__ float blocksum128(float v, float* sb) {
    #pragma unroll
    for (int o = 16; o; o >>= 1) v += __shfl_xor_sync(0xffffffffu, v, o);
    if ((threadIdx.x & 31) == 0) sb[threadIdx.x >> 5] = v;
    __syncthreads();
    float r = sb[0] + sb[1] + sb[2] + sb[3];
    __syncthreads();
    return r;
}

// ---------------- K1: embedding gather + LayerNorm1 ----------------
__global__ void embed_ln1(const int* __restrict__ seqs,
                          const float* __restrict__ g1, const float* __restrict__ b1,
                          float* __restrict__ xout) {
    __shared__ float sb[4];
    int idx = blockIdx.x;            // b*TT + t
    int b = idx / TT, t = idx - b * TT;
    int tid = threadIdx.x;           // 128
    int tok = seqs[b * (TT + 1) + t];
    float e  = d_embT[(size_t)tok * HH + tid];
    float mu = blocksum128(e, sb) * (1.0f / HH);
    float d  = e - mu;
    float var = blocksum128(d * d, sb) * (1.0f / HH);
    float xn = d * rsqrtf(var + 1e-8f) * g1[tid] + b1[tid];
    xout[(size_t)idx * HH + tid] = xn;
}

// ---------------- K2: gi = x @ Wih^T + bih  (M=102400, N=384, K=128) ----------------
// 128m x 64n tiles, 256 threads, 2 CTAs/SM, packed f32x2 FMA.
#define GPA 132   // As pitch (floats)
#define GPB 68    // Bs pitch (floats)
__global__ __launch_bounds__(256, 2)
void gemm_gi(const float* __restrict__ x, const float* __restrict__ wT,
             const float* __restrict__ bih, float* __restrict__ gi) {
    extern __shared__ float smem[];
    float* As = smem;            // [m 0..127][k pitch GPA]
    float* Bs = smem + 128 * GPA;// [k 0..127][n pitch GPB]
    int tid = threadIdx.x;
    int tx = tid & 7, ty = tid >> 3;       // tx: n-group (0..7), ty: m-group (0..31)
    int m0 = blockIdx.x * 128;
    int n0 = blockIdx.y * 64;

    // load A tile (float4, direct copy)
    #pragma unroll
    for (int i = tid; i < 128 * 32; i += 256) {
        int m = i >> 5, k4 = i & 31;
        float4 v = *(const float4*)&x[((size_t)(m0 + m)) * 128 + k4 * 4];
        *(float4*)&As[m * GPA + k4 * 4] = v;
    }
    // load B tile (k-major from pre-transposed WihT)
    #pragma unroll
    for (int i = tid; i < 128 * 16; i += 256) {
        int k = i >> 4, n4 = i & 15;
        float4 v = *(const float4*)&wT[(size_t)k * G3 + n0 + n4 * 4];
        *(float4*)&Bs[k * GPB + n4 * 4] = v;
    }
    __syncthreads();

    // acc[i][p]: 4 m-rows x 4 packed n-pairs (n: tx*4+{0,1},{2,3}, 32+tx*4+{0,1},{2,3})
    unsigned long long acc[4][4];
    #pragma unroll
    for (int i = 0; i < 4; i++)
        #pragma unroll
        for (int p = 0; p < 4; p++) acc[i][p] = 0ull;

    #pragma unroll 8
    for (int kc = 0; kc < 32; kc++) {
        float4 a4[4];
        #pragma unroll
        for (int i = 0; i < 4; i++)
            a4[i] = *(const float4*)&As[(ty * 4 + i) * GPA + kc * 4];
        #pragma unroll
        for (int kk = 0; kk < 4; kk++) {
            int krow = kc * 4 + kk;
            ulonglong2 bl = *(const ulonglong2*)&Bs[krow * GPB + tx * 4];
            ulonglong2 bh = *(const ulonglong2*)&Bs[krow * GPB + 32 + tx * 4];
            #pragma unroll
            for (int i = 0; i < 4; i++) {
                float av = (kk == 0) ? a4[i].x : (kk == 1) ? a4[i].y
                         : (kk == 2) ? a4[i].z : a4[i].w;
                unsigned long long ap = f2dup(av);
                FMA2(acc[i][0], ap, bl.x);
                FMA2(acc[i][1], ap, bl.y);
                FMA2(acc[i][2], ap, bh.x);
                FMA2(acc[i][3], ap, bh.y);
            }
        }
    }

    // bias values for this thread's 8 n-columns
    float bv[8];
    #pragma unroll
    for (int j = 0; j < 4; j++) {
        bv[j]     = bih[n0 + tx * 4 + j];
        bv[4 + j] = bih[n0 + 32 + tx * 4 + j];
    }

    #pragma unroll
    for (int i = 0; i < 4; i++) {
        size_t m = m0 + ty * 4 + i;
        float* grow = &gi[m * G3 + n0];
        #pragma unroll
        for (int p = 0; p < 4; p++) {
            float lo, hi;
            f2unpack(acc[i][p], lo, hi);
            int nb = (p < 2) ? (tx * 4 + p * 2) : (32 + tx * 4 + (p - 2) * 2);
            float2 st = make_float2(lo + bv[(p < 2) ? p * 2 : 4 + (p - 2) * 2],
                                    hi + bv[(p < 2) ? p * 2 + 1 : 4 + (p - 2) * 2 + 1]);
            *(float2*)&grow[nb] = st;
        }
    }
}

// ---------------- K3: GRU recurrence ----------------
// 256 CTAs x 2 sequences, 384 threads. Whh row held in REGISTERS (const across
// 200 steps), packed f32x2 FMA. h broadcast from smem.
__global__ __launch_bounds__(384, 1)
void gru_rec(const float* __restrict__ gi, const float* __restrict__ Whh,
             const float* __restrict__ bhh, float* __restrict__ hs) {
    __shared__ float hsh[2 * 128];
    __shared__ float ghsh[2 * 384];
    int tid = threadIdx.x;             // 384 = one Whh row per thread
    int s0  = blockIdx.x * 2;

    // load this thread's Whh row into registers (packed pairs over k)
    unsigned long long w[64];
    {
        const ulonglong2* wp = (const ulonglong2*)(Whh + (size_t)tid * 128);
        #pragma unroll
        for (int i = 0; i < 32; i++) {
            ulonglong2 v = wp[i];
            w[2 * i]     = v.x;
            w[2 * i + 1] = v.y;
        }
    }

    int su = tid >> 7, ju = tid & 127;   // update-phase mapping (tid < 256)
    float bhr = 0.f, bhz = 0.f, bhn = 0.f;
    const float* gp = nullptr;
    float* hp = nullptr;
    float hreg = 0.f;
    if (tid < 256) {
        bhr = bhh[ju]; bhz = bhh[128 + ju]; bhn = bhh[256 + ju];
        gp = gi + ((size_t)(s0 + su) * TT) * G3 + ju;
        hp = hs + ((size_t)(s0 + su) * TT) * HH + ju;
        hsh[su * 128 + ju] = 0.f;
    }
    __syncthreads();

    for (int t = 0; t < TT; t++) {
        // prefetch gi for the update phase (hides L2 latency under dot phase)
        float ir = 0.f, iz = 0.f, inn = 0.f;
        if (tid < 256) {
            ir  = gp[0];
            iz  = gp[128];
            inn = gp[256];
        }

        // dot phase: gh[s][tid] = Whh[tid] . h[s]
        unsigned long long a0a = 0ull, a0b = 0ull, a1a = 0ull, a1b = 0ull;
        const ulonglong2* h0p = (const ulonglong2*)&hsh[0];
        const ulonglong2* h1p = (const ulonglong2*)&hsh[128];
        #pragma unroll
        for (int k4 = 0; k4 < 32; k4++) {
            ulonglong2 h0 = h0p[k4];
            ulonglong2 h1 = h1p[k4];
            FMA2(a0a, w[2 * k4],     h0.x);
            FMA2(a0b, w[2 * k4 + 1], h0.y);
            FMA2(a1a, w[2 * k4],     h1.x);
            FMA2(a1b, w[2 * k4 + 1], h1.y);
        }
        ghsh[tid]       = f2sum(a0a) + f2sum(a0b);
        ghsh[384 + tid] = f2sum(a1a) + f2sum(a1b);
        __syncthreads();

        // update phase
        if (tid < 256) {
            const float* gh = &ghsh[su * 384];
            float hr = gh[ju]       + bhr;
            float hz = gh[128 + ju] + bhz;
            float hn = gh[256 + ju] + bhn;
            float r = 1.f / (1.f + __expf(-(ir + hr)));
            float z = 1.f / (1.f + __expf(-(iz + hz)));
            float n = tanhf(inn + r * hn);
            float hnew = (1.f - z) * n + z * hreg;
            hreg = hnew;
            hsh[su * 128 + ju] = hnew;
            *hp = hnew;
            gp += G3;
            hp += HH;
        }
        __syncthreads();
    }
}

// ---------------- K4: LayerNorm2 + pos/neg dot products ----------------
__global__ void final_logits(const int* __restrict__ seqs, const int* __restrict__ negs,
                             const float* __restrict__ g2, const float* __restrict__ b2,
                             float* __restrict__ out) {
    __shared__ float sb[4];
    int idx = blockIdx.x;
    int b = idx / TT, t = idx - b * TT;
    int tid = threadIdx.x;          // 128
    float v  = d_hs[(size_t)idx * HH + tid];
    float mu = blocksum128(v, sb) * (1.0f / HH);
    float d  = v - mu;
    float var = blocksum128(d * d, sb) * (1.0f / HH);
    float ln = d * rsqrtf(var + 1e-8f) * g2[tid] + b2[tid];

    int pt = seqs[b * (TT + 1) + t + 1];
    int nt = negs[b * (TT + 1) + t + 1];
    float pv = ln * d_embT[(size_t)pt * HH + tid];
    float nv = ln * d_embT[(size_t)nt * HH + tid];
    float ps = blocksum128(pv, sb);
    float ns = blocksum128(nv, sb);
    if (tid == 0) {
        out[idx]           = ps;
        out[M_TOTAL + idx] = ns;
    }
}

// ---------------- launch ----------------
extern "C" void kernel_launch(void* const* d_in, const int* in_sizes, int n_in,
                              void* d_out, int out_size) {
    const int*   input_seqs = (const int*)  d_in[0];
    const int*   negs       = (const int*)  d_in[1];
    const float* emb_W      = (const float*)d_in[2];
    const float* Wih        = (const float*)d_in[3];
    const float* Whh        = (const float*)d_in[4];
    const float* bih        = (const float*)d_in[5];
    const float* bhh        = (const float*)d_in[6];
    const float* ln1_g      = (const float*)d_in[7];
    const float* ln1_b      = (const float*)d_in[8];
    const float* ln2_g      = (const float*)d_in[9];
    const float* ln2_b      = (const float*)d_in[10];
    float* out = (float*)d_out;

    float* p_embT; cudaGetSymbolAddress((void**)&p_embT, d_embT);
    float* p_x;    cudaGetSymbolAddress((void**)&p_x,    d_x);
    float* p_gi;   cudaGetSymbolAddress((void**)&p_gi,   d_gi);
    float* p_hs;   cudaGetSymbolAddress((void**)&p_hs,   d_hs);
    float* p_WihT; cudaGetSymbolAddress((void**)&p_WihT, d_WihT);

    transpose_kernel<<<dim3((VV + 31) / 32, 4), dim3(32, 8)>>>(emb_W, p_embT, HH, VV);
    transpose_kernel<<<dim3(4, 12), dim3(32, 8)>>>(Wih, p_WihT, G3, HH);

    embed_ln1<<<M_TOTAL, 128>>>(input_seqs, ln1_g, ln1_b, p_x);

    const int gemm_smem = (128 * GPA + 128 * GPB) * sizeof(float);   // 102400 B
    cudaFuncSetAttribute(gemm_gi, cudaFuncAttributeMaxDynamicSharedMemorySize, gemm_smem);
    gemm_gi<<<dim3(M_TOTAL / 128, G3 / 64), 256, gemm_smem>>>(p_x, p_WihT, bih, p_gi);

    gru_rec<<<BB / 2, 384>>>(p_gi, Whh, bhh, p_hs);

    final_logits<<<M_TOTAL, 128>>>(input_seqs, negs, ln2_g, ln2_b, out);
}